// round 13
// baseline (speedup 1.0000x reference)
#include <cuda_runtime.h>
#include <math.h>
#include <limits.h>
#include <stdint.h>

// Problem constants
#define TT   10000
#define BB   4096
#define CH   8              // t-rows per chunk
#define KGX  4              // lane groups (KGX*1024 == BB)
#define KGY  138            // chunk groups (covers ta <= 1104 in one shot)
#define NBLK (KGX * KGY)    // kill blocks; +1 scan block
#define NTHR 256
#define EPT  40             // scan: elements per thread (250 active threads)
#define LCAP 1024           // per-chunk candidate capacity

#define LOG_GAMMA_C ( 0.019802627296179713f)   // ln(1.02)
#define ALPHA_C     (-1.0050335853501451e-05f) // ln(0.99)/1000
#define INIT_LOGW_C (-1.3943265327605025f)     // ln(0.248)
#define INIT_LOGP_C (-6.907755278982137f)      // ln(0.001)
#define INV_TEMP_C  (0.001f)
#define EPSF        (1e-12f)

// Persistent device state. INVARIANT: all-zero at kernel entry and exit
// (zero static init; last finishing block restores zeros), so graph replays
// are deterministic. g_tk encoding: value v = max over kills of (TT - t);
// v == 0 means "never killed"; t_kill = TT - v.
__device__ float2       g_row[TT];      // {thr, rm}: u2 filter threshold, r - eps
__device__ float        g_pref[TT + 1]; // exclusive prefix of W_t
__device__ int          g_tactive;
__device__ int          g_tk[BB];
__device__ unsigned int g_done;
__device__ int          g_ready;

// ---------------------------------------------------------------------------
// PTX helpers: bulk async copy + mbarrier
// ---------------------------------------------------------------------------
__device__ __forceinline__ void mbar_init(uint32_t addr, uint32_t cnt) {
    asm volatile("mbarrier.init.shared.b64 [%0], %1;" :: "r"(addr), "r"(cnt) : "memory");
}
__device__ __forceinline__ void mbar_expect_tx(uint32_t addr, uint32_t bytes) {
    asm volatile("mbarrier.arrive.expect_tx.shared.b64 _, [%0], %1;"
                 :: "r"(addr), "r"(bytes) : "memory");
}
__device__ __forceinline__ void mbar_wait(uint32_t addr, uint32_t parity) {
    asm volatile(
        "{\n\t"
        ".reg .pred P1;\n\t"
        "WAIT_LOOP_%=:\n\t"
        "mbarrier.try_wait.parity.acquire.cta.shared::cta.b64 P1, [%0], %1, 0x989680;\n\t"
        "@P1 bra.uni WAIT_DONE_%=;\n\t"
        "bra.uni WAIT_LOOP_%=;\n\t"
        "WAIT_DONE_%=:\n\t"
        "}"
        :: "r"(addr), "r"(parity) : "memory");
}
__device__ __forceinline__ void cp_bulk4k(uint32_t sdst, const void* g, uint32_t mbar) {
    asm volatile(
        "cp.async.bulk.shared::cta.global.mbarrier::complete_tx::bytes [%0], [%1], %2, [%3];"
        :: "r"(sdst), "l"(g), "r"(4096u), "r"(mbar) : "memory");
}

// ---------------------------------------------------------------------------
// Block-wide exclusive scan, 8 warps (256 threads)
// ---------------------------------------------------------------------------
__device__ __forceinline__ float block_exscan8(float v, float* ws) {
    const int lane = threadIdx.x & 31;
    const int wid  = threadIdx.x >> 5;
    float s = v;
#pragma unroll
    for (int o = 1; o < 32; o <<= 1) {
        float n = __shfl_up_sync(0xffffffffu, s, o);
        if (lane >= o) s += n;
    }
    float exw = __shfl_up_sync(0xffffffffu, s, 1);
    if (lane == 0) exw = 0.0f;
    if (lane == 31) ws[wid] = s;
    __syncthreads();
    if (wid == 0) {
        float t = (lane < 8) ? ws[lane] : 0.0f;
#pragma unroll
        for (int o = 1; o < 8; o <<= 1) {
            float n = __shfl_up_sync(0xffffffffu, t, o);
            if (lane >= o) t += n;
        }
        float exb = __shfl_up_sync(0xffffffffu, t, 1);
        if (lane == 0) exb = 0.0f;
        if (lane < 8) ws[lane] = exb;
    }
    __syncthreads();
    return ws[wid] + exw;
}

// ---------------------------------------------------------------------------
// Single fused kernel.
//  block 0           : scan (per-t tables from acts), sets g_ready
//  blocks 1..NBLK    : prefetch u2 chunk via cp.async.bulk, spin on g_ready,
//                      two-phase kill search, ticketed final reduction
// ---------------------------------------------------------------------------
__global__ void __launch_bounds__(NTHR, 4)
fused_kernel(const float* __restrict__ acts, const float* __restrict__ u1,
             const float* __restrict__ u2, float* __restrict__ out) {
    __shared__ __align__(16) char s_raw[40960];  // scan: f[10000] | kill: u2 32K + lists 8K
    __shared__ float2 s_row[CH];
    __shared__ float  s_ws[32];
    __shared__ unsigned long long s_mbar;
    __shared__ int  s_cnt, sh_ta;
    __shared__ bool s_last;

    const int tid = threadIdx.x;
    const int bid = blockIdx.x;

    // ======================= SCAN BLOCK =======================
    if (bid == 0) {
        // stage f = exp(acts) into smem (coalesced float4)
        {
            const float4* a4 = (const float4*)acts;
            float4* f4 = (float4*)s_raw;
            for (int i = tid; i < TT / 4; i += NTHR) {
                float4 a = a4[i];
                f4[i] = make_float4(__expf(a.x), __expf(a.y), __expf(a.z), __expf(a.w));
            }
        }
        __syncthreads();
        const float* s_f = (const float*)s_raw;
        const int  base = tid * EPT;
        const bool act  = (base < TT);

        // pass 1: per-thread csum
        float csum = 0.0f;
        if (act) {
#pragma unroll 4
            for (int i = 0; i < EPT; ++i)
                csum += LOG_GAMMA_C + __logf(1.0f - s_f[base + i]);
        }
        const float coff = block_exscan8(act ? csum : 0.0f, s_ws);
        const float lw0  = INIT_LOGW_C + coff;

        // pass 2: dsum / wsum (recurrences recomputed identically in pass 3)
        float dsum = 0.0f, wsum = 0.0f;
        if (act) {
            float elw = __expf(lw0), wv = __expf(lw0 * INV_TEMP_C), lwl = 0.0f;
#pragma unroll 4
            for (int i = 0; i < EPT; ++i) {
                float fv = s_f[base + i];
                float c  = LOG_GAMMA_C + __logf(1.0f - fv);
                dsum += ALPHA_C * fv * elw;
                elw  *= 1.02f * (1.0f - fv);
                lwl  += c;
                float x = lwl * INV_TEMP_C;
                wsum += wv * (1.0f + x * (1.0f + 0.5f * x));
            }
        }
        const float doff = block_exscan8(act ? dsum : 0.0f, s_ws);
        const float woff = block_exscan8(act ? wsum : 0.0f, s_ws);

        // pass 3: emit tables.  e = exp(logp) <= 1e-3 always, so log1p(-e),
        // e/(1-e), exp(-28r) are tiny-argument polynomials (abs err <= 3e-8).
        int poss = -1;
        if (act) {
            float elw = __expf(lw0), wv = __expf(lw0 * INV_TEMP_C), lwl = 0.0f;
            float lp = INIT_LOGP_C + doff, pw = woff;
#pragma unroll 4
            for (int i = 0; i < EPT; ++i) {
                float fv = s_f[base + i];
                float c  = LOG_GAMMA_C + __logf(1.0f - fv);
                float dd = ALPHA_C * fv * elw;
                elw *= 1.02f * (1.0f - fv);
                lwl += c;
                float x = lwl * INV_TEMP_C;
                float ww = wv * (1.0f + x * (1.0f + 0.5f * x));
                g_pref[base + i] = pw;  pw += ww;
                float e = __expf(lp);
                float logit = lp + e * (1.0f + 0.5f * e);
                float r = e * (1.0f + e);
                // kill requires u2 + eps > exp(-27.631*r); 28 / -1e-5 margins
                float xx = 28.0f * r;
                float thr = 1.0f - xx * (1.0f - 0.5f * xx * (1.0f - 0.33333334f * xx)) - 1e-5f;
                g_row[base + i] = make_float2(thr, r - EPSF);
                if (logit > -20.5f) poss = base + i;  // noise <= 19.95 always
                lp += dd;
            }
            if (base + EPT == TT) g_pref[TT] = pw;
        }

        if (tid == 0) sh_ta = 0;
        __syncthreads();
        if (poss >= 0) atomicMax(&sh_ta, poss + 1);
        __syncthreads();
        if (tid == 0) {
            g_tactive = sh_ta;
            __threadfence();
            atomicExch(&g_ready, 1);   // release tables to kill blocks
        }
        return;
    }

    // ======================= KILL BLOCKS =======================
    const int kid = bid - 1;
    const int kx  = kid & (KGX - 1);       // lane group: lanes [kx*1024, +1024)
    const int ky  = kid >> 2;              // chunk group
    const uint32_t sm_u2 = (uint32_t)__cvta_generic_to_shared(s_raw);
    const uint32_t mb    = (uint32_t)__cvta_generic_to_shared(&s_mbar);
    float*    s_val = (float*)(s_raw + 32768);
    uint32_t* s_pk  = (uint32_t*)(s_raw + 36864);

    if (tid == 0) mbar_init(mb, 1);
    __syncthreads();

    // prefetch first chunk immediately (independent of scan results)
    if (tid == 0) {
        mbar_expect_tx(mb, CH * 4096u);
        const char* gb = (const char*)u2;
#pragma unroll
        for (int i = 0; i < CH; ++i) {
            int tt = min(ky * CH + i, TT - 1);
            cp_bulk4k(sm_u2 + i * 4096u, gb + ((size_t)tt * BB + kx * 1024) * 4u, mb);
        }
    }

    // wait for scan tables (overlaps with the DMA above)
    if (tid == 0) { while (atomicAdd(&g_ready, 0) == 0) __nanosleep(64); }
    __syncthreads();
    __threadfence();
    const int ta      = g_tactive;
    const int nchunks = (ta + CH - 1) / CH;

    // always consume the prefetched chunk's completion (even if unused)
    uint32_t phase = 0;
    mbar_wait(mb, phase); phase ^= 1u;

    for (int cy = ky; cy < nchunks; cy += KGY) {
        const int t0 = cy * CH;
        if (cy != ky) {
            __syncthreads();               // everyone done with previous s_u2/lists
            if (tid == 0) {
                mbar_expect_tx(mb, CH * 4096u);
                const char* gb = (const char*)u2;
#pragma unroll
                for (int i = 0; i < CH; ++i) {
                    int tt = min(t0 + i, TT - 1);
                    cp_bulk4k(sm_u2 + i * 4096u, gb + ((size_t)tt * BB + kx * 1024) * 4u, mb);
                }
            }
        }
        if (tid == 0) s_cnt = 0;
        if (tid < CH) s_row[tid] = g_row[min(t0 + tid, TT - 1)];
        if (cy != ky) { mbar_wait(mb, phase); phase ^= 1u; }
        __syncthreads();

        const int rmax = min(CH, ta - t0);
        const float4* u2s = (const float4*)s_raw;
        // ---- Phase A: pure filter, append candidates (no global loads) ----
#pragma unroll
        for (int i = 0; i < CH; ++i) {
            if (i >= rmax) break;
            const float  thr = s_row[i].x;
            const float4 vv  = u2s[i * 256 + tid];
            const float  m   = fmaxf(fmaxf(vv.x, vv.y), fmaxf(vv.z, vv.w));
            if (m > thr) {
                const uint32_t pkb = ((uint32_t)i << 10) | ((uint32_t)tid << 2);
                float vs[4] = {vv.x, vv.y, vv.z, vv.w};
#pragma unroll
                for (int sub = 0; sub < 4; ++sub) {
                    if (vs[sub] > thr) {
                        int slot = atomicAdd(&s_cnt, 1);
                        if (slot < LCAP) {
                            s_val[slot] = vs[sub];
                            s_pk[slot]  = pkb | (uint32_t)sub;
                        } else {   // statistically-never fallback: direct eval
                            int gl = kx * 1024 + (int)(pkb & 1023u) + sub;
                            float L1 = __logf(u1[(t0 + i) * BB + gl] + EPSF);
                            float L2 = __logf(vs[sub] + EPSF);
                            if (L2 > s_row[i].y * L1) atomicMax(&g_tk[gl], TT - (t0 + i));
                        }
                    }
                }
            }
        }
        __syncthreads();

        // ---- Phase B: burst evaluation (all u1 loads in one round) ----
        // exact: sigmoid(logit+noise)>0.5 <=> L2/L1+eps < r <=> L2 > (r-eps)*L1
        const int n = min(s_cnt, LCAP);
        for (int j = tid; j < n; j += NTHR) {
            const uint32_t pk = s_pk[j];
            const int i  = (int)(pk >> 10);
            const int gl = kx * 1024 + (int)(pk & 1023u);
            const int t  = t0 + i;
            float L1 = __logf(u1[t * BB + gl] + EPSF);
            float L2 = __logf(s_val[j] + EPSF);
            if (L2 > s_row[i].y * L1) atomicMax(&g_tk[gl], TT - t);
        }
    }

    // ---- ticketed final reduction + state reset (keeps zero-invariant) ----
    __threadfence();
    if (tid == 0) s_last = (atomicAdd(&g_done, 1u) == NBLK - 1u);
    __syncthreads();
    if (!s_last) return;
    __threadfence();

    int kk[BB / NTHR];
#pragma unroll
    for (int it = 0; it < BB / NTHR; ++it) kk[it] = g_tk[tid + it * NTHR];
#pragma unroll
    for (int it = 0; it < BB / NTHR; ++it) g_tk[tid + it * NTHR] = 0;  // reset
    double s = 0.0;
#pragma unroll
    for (int it = 0; it < BB / NTHR; ++it) s += (double)g_pref[TT - kk[it]];

    double* sh = (double*)s_raw;
    sh[tid] = s;
    __syncthreads();
#pragma unroll
    for (int off = 128; off > 0; off >>= 1) {
        if (tid < off) sh[tid] += sh[tid + off];
        __syncthreads();
    }
    if (tid == 0) {
        out[0] = (float)(sh[0] / (double)BB);
        g_done  = 0u;
        g_ready = 0;
    }
}

// ---------------------------------------------------------------------------
extern "C" void kernel_launch(void* const* d_in, const int* in_sizes, int n_in,
                              void* d_out, int out_size) {
    const float* acts = (const float*)d_in[0];
    const float* u1   = (const float*)d_in[1];
    const float* u2   = (const float*)d_in[2];

    fused_kernel<<<NBLK + 1, NTHR>>>(acts, u1, u2, (float*)d_out);
}